// round 7
// baseline (speedup 1.0000x reference)
#include <cuda_runtime.h>
#include <cuda_bf16.h>
#include <cuda_fp16.h>
#include <cuda_fp8.h>
#include <stdint.h>
#include <math.h>

// Problem dims (fixed by the dataset)
#define B    32
#define NIN  2312
#define NHID 512
#define NOUT 10
#define TT   350
#define NCOL (B * TT)   // 11200 (b, t) columns
#define NCHK 8          // input chunks for parallel pack
#define CE   289        // NIN / NCHK
#define SUBN 48         // max events per (col, chunk); mean ~8.7
#define MAXTOT (NCHK * SUBN)   // 384
#define WSCALE 64.0f    // fp8 weight scale (power of two -> exact rescale)
#define WINV   0.015625f

// ---------------- device scratch (static, no allocation) ----------------
__device__ __align__(256) unsigned char g_W1T8[NIN * NHID];  // 1.18 MB fp8 e4m3 weights (x64)
__device__            int  g_cntc[NCOL * NCHK];
__device__            int  g_idx[NCOL * MAXTOT];
__device__ __align__(256) float g_z1[NCOL * NHID];           // [(b*T+t)*NHID + o]
__device__ __align__(256) float g_s1[NCOL * NHID];
__device__ __align__(256) float g_z2[NCOL * NOUT];

// ---------------- 1) W1 (NHID x NIN) -> W1T fp8 (NIN x NHID), scaled by 64 ----------------
__global__ void k_transpose(const float* __restrict__ W1) {
    __shared__ float tile[32][33];
    int o0 = blockIdx.x * 32;
    int i0 = blockIdx.y * 32;
    int tx = threadIdx.x, ty = threadIdx.y;  // (32, 8)
#pragma unroll
    for (int k = 0; k < 4; k++) {
        int o = o0 + ty + 8 * k;
        int i = i0 + tx;
        tile[ty + 8 * k][tx] = (i < NIN) ? W1[(size_t)o * NIN + i] : 0.f;
    }
    __syncthreads();
#pragma unroll
    for (int k = 0; k < 4; k++) {
        int i = i0 + ty + 8 * k;
        int o = o0 + tx;
        if (i < NIN)
            g_W1T8[(size_t)i * NHID + o] =
                __nv_cvt_float_to_fp8(tile[tx][ty + 8 * k] * WSCALE, __NV_SATFINITE, __NV_E4M3);
    }
}

// ---------------- 2) pack input events (parallel over 8 input chunks) ----------------
__global__ void __launch_bounds__(256) k_pack(const float* __restrict__ x) {
    int b  = blockIdx.x;
    int t0 = blockIdx.y * 32;
    int tx = threadIdx.x & 31;
    int c  = threadIdx.x >> 5;
    int t  = t0 + tx;
    if (t >= TT) return;
    int col = b * TT + t;
    const float* px = x + (size_t)b * NIN * TT + t;
    int base = col * MAXTOT + c * SUBN;
    int n = 0;
#pragma unroll 8
    for (int k = 0; k < CE; k++) {
        int i = c * CE + k;
        if (px[(size_t)i * TT] != 0.f) {
            if (n < SUBN) g_idx[base + n] = i;
            n++;
        }
    }
    g_cntc[col * NCHK + c] = (n < SUBN) ? n : SUBN;
}

// ---------------- 3) sparse gather: warp-wide rows, LDG.128, half2 accumulation ----------------
// Per event, ONE warp loads the whole 512B fp8 row with one LDG.128/thread (16 outputs/thread).
// 4 warps split the event list; partial sums combined via smem. z1 = (1/64) * sum.
__global__ void __launch_bounds__(128) k_gather() {
    int col = blockIdx.x;
    __shared__ int sh[MAXTOT];
    __shared__ int offs[NCHK + 1];
    __shared__ float partial[4][NHID];   // 8 KB
    if (threadIdx.x == 0) {
        int acc = 0;
#pragma unroll
        for (int c = 0; c < NCHK; c++) { offs[c] = acc; acc += g_cntc[col * NCHK + c]; }
        offs[NCHK] = acc;
    }
    __syncthreads();
    {   // compact the 8 sub-lists into sh[0..cnt)
        int c = threadIdx.x >> 4, jj = threadIdx.x & 15;
        int o0 = offs[c], cc = offs[c + 1] - o0;
        for (int j = jj; j < cc; j += 16) sh[o0 + j] = g_idx[col * MAXTOT + c * SUBN + j];
    }
    __syncthreads();
    int cnt = offs[NCHK];
    int w = threadIdx.x >> 5, lane = threadIdx.x & 31;

    // 8 half2 accumulators = 16 outputs per thread; 2-way event unroll
    __half2 accA[8], accB[8];
#pragma unroll
    for (int k = 0; k < 8; k++) { accA[k] = __half2half2(__ushort_as_half(0)); accB[k] = accA[k]; }

#define DECODE_ADD(ACC, V) { \
        unsigned int uu[4] = {__float_as_uint((V).x), __float_as_uint((V).y), \
                              __float_as_uint((V).z), __float_as_uint((V).w)}; \
        _Pragma("unroll") \
        for (int q = 0; q < 4; q++) { \
            __half2_raw lo = __nv_cvt_fp8x2_to_halfraw2((__nv_fp8x2_storage_t)(uu[q] & 0xFFFFu), __NV_E4M3); \
            __half2_raw hi = __nv_cvt_fp8x2_to_halfraw2((__nv_fp8x2_storage_t)(uu[q] >> 16),    __NV_E4M3); \
            ACC[2*q]   = __hadd2(ACC[2*q],   *(__half2*)&lo); \
            ACC[2*q+1] = __hadd2(ACC[2*q+1], *(__half2*)&hi); \
        } }

    int j = w;
    for (; j + 4 < cnt; j += 8) {   // two events per iteration (this warp's share)
        float4 v0 = *(const float4*)(g_W1T8 + (size_t)sh[j] * NHID + lane * 16);
        float4 v1 = *(const float4*)(g_W1T8 + (size_t)sh[j + 4] * NHID + lane * 16);
        DECODE_ADD(accA, v0)
        DECODE_ADD(accB, v1)
    }
    if (j < cnt) {
        float4 v0 = *(const float4*)(g_W1T8 + (size_t)sh[j] * NHID + lane * 16);
        DECODE_ADD(accA, v0)
    }
#undef DECODE_ADD

    // write this warp's 16 fp32 partials to smem
#pragma unroll
    for (int k = 0; k < 8; k++) {
        float2 fa = __half22float2(accA[k]);
        float2 fb = __half22float2(accB[k]);
        partial[w][lane * 16 + 2 * k]     = fa.x + fb.x;
        partial[w][lane * 16 + 2 * k + 1] = fa.y + fb.y;
    }
    __syncthreads();

    // cross-warp reduce: 128 threads x 4 outputs each
    float* zo = g_z1 + (size_t)col * NHID;
#pragma unroll
    for (int q = 0; q < 4; q++) {
        int o = threadIdx.x + 128 * q;
        float s = (partial[0][o] + partial[1][o]) + (partial[2][o] + partial[3][o]);
        zo[o] = s * WINV;
    }
}

// ---------------- 4) fused psp + spike (R2 schedule: 8-deep prefetch, dual global reads) -------
// psp kernel k[j] = (e/10)*j*d^j, d=exp(-0.1), truncated to j in [0,76].
// psp[t] = (e/10)*( y[t] - d^77*( y2[t] + 77*x2[t] ) ), (x2,y2) fed by z[t-77].
__device__ __forceinline__ void rec_core(const float* __restrict__ zin,
                                         float* __restrict__ sout,
                                         int C, int outMode, int gid) {
    const float d    = (float)exp(-0.1);
    const float D77  = (float)exp(-7.7);
    const float coef = (float)(exp(1.0) / 10.0);
    const float DR   = (float)exp(-1.0);
    const float CR   = (float)(-20.0 * exp(1.0));

    int b = gid / C, o = gid % C;
    const float* p = zin + (size_t)b * TT * C + o;

    float x = 0.f, y = 0.f, x2 = 0.f, y2 = 0.f, xr = 0.f, yr = 0.f;
    float cur[8], curd[8];
#pragma unroll
    for (int k = 0; k < 8; k++) { cur[k] = p[(size_t)k * C]; curd[k] = 0.f; }

    for (int tb = 0; tb < 352; tb += 8) {
        float nxt[8], nxtd[8];
#pragma unroll
        for (int k = 0; k < 8; k++) {
            int t2 = tb + 8 + k;
            nxt[k] = (t2 < TT) ? p[(size_t)t2 * C] : 0.f;
            int td = t2 - 77;
            nxtd[k] = (td >= 0 && td < TT) ? p[(size_t)td * C] : 0.f;
        }
#pragma unroll
        for (int k = 0; k < 8; k++) {
            int t = tb + k;
            if (t < TT) {
                y  = d * (y  + x );  x  = d * x  + cur[k];
                y2 = d * (y2 + x2);  x2 = d * x2 + curd[k];
                float pp = coef * (y - D77 * (y2 + 77.f * x2));
                yr = DR * (yr + xr);
                float u = pp + CR * yr;
                float spk = (u >= 10.f) ? 1.f : 0.f;
                xr = DR * xr + spk;
                size_t oidx = outMode ? ((size_t)(b * C + o) * TT + t)
                                      : ((size_t)(b * TT + t) * C + o);
                sout[oidx] = spk;
            }
        }
#pragma unroll
        for (int k = 0; k < 8; k++) { cur[k] = nxt[k]; curd[k] = nxtd[k]; }
    }
}

__global__ void __launch_bounds__(128) k_rec1() {
    int gid = blockIdx.x * 128 + threadIdx.x;
    if (gid >= B * NHID) return;
    rec_core(g_z1, g_s1, NHID, 0, gid);
}

__global__ void __launch_bounds__(128) k_rec2(float* __restrict__ out) {
    int gid = blockIdx.x * 128 + threadIdx.x;
    if (gid >= B * NOUT) return;
    rec_core(g_z2, out, NOUT, 1, gid);
}

// ---------------- 5) layer-2 GEMV: W2 in smem, s1 read once, all-zero fast path ----------------
__global__ void __launch_bounds__(128) k_gemv2(const float* __restrict__ W2) {
    __shared__ float w2s[NOUT * NHID];   // 20 KB
    for (int i = threadIdx.x; i < NOUT * NHID; i += 128) w2s[i] = W2[i];
    __syncthreads();
    int w = threadIdx.x >> 5, lane = threadIdx.x & 31;
    for (int col = blockIdx.x * 4 + w; col < NCOL; col += gridDim.x * 4) {
        const float4* sp = (const float4*)(g_s1 + (size_t)col * NHID);
        float4 s[4];
        float ssum = 0.f;
#pragma unroll
        for (int q = 0; q < 4; q++) {
            s[q] = sp[lane + 32 * q];
            ssum += s[q].x + s[q].y + s[q].z + s[q].w;
        }
        if (!__any_sync(0xffffffffu, ssum != 0.f)) {
            if (lane < NOUT) g_z2[(size_t)col * NOUT + lane] = 0.f;
            continue;
        }
#pragma unroll
        for (int ww = 0; ww < NOUT; ww++) {
            float sum = 0.f;
#pragma unroll
            for (int q = 0; q < 4; q++) {
                const float4 wv = *(const float4*)&w2s[ww * NHID + (lane + 32 * q) * 4];
                sum += wv.x * s[q].x + wv.y * s[q].y + wv.z * s[q].z + wv.w * s[q].w;
            }
#pragma unroll
            for (int off = 16; off; off >>= 1) sum += __shfl_xor_sync(0xffffffffu, sum, off);
            if (lane == 0) g_z2[(size_t)col * NOUT + ww] = sum;
        }
    }
}

// ---------------- launch ----------------
extern "C" void kernel_launch(void* const* d_in, const int* in_sizes, int n_in,
                              void* d_out, int out_size) {
    const float* x  = (const float*)d_in[0];   // (32, 2312, 350)
    const float* W1 = (const float*)d_in[1];   // (512, 2312)
    const float* W2 = (const float*)d_in[2];   // (10, 512)
    float* out = (float*)d_out;                // (32, 10, 350)

    k_transpose<<<dim3(NHID / 32, (NIN + 31) / 32), dim3(32, 8)>>>(W1);
    k_pack<<<dim3(B, (TT + 31) / 32), 256>>>(x);
    k_gather<<<NCOL, 128>>>();
    k_rec1<<<(B * NHID) / 128, 128>>>();
    k_gemv2<<<700, 128>>>(W2);
    k_rec2<<<(B * NOUT + 127) / 128, 128>>>(out);
}

// round 8
// speedup vs baseline: 1.0655x; 1.0655x over previous
#include <cuda_runtime.h>
#include <cuda_bf16.h>
#include <cuda_fp8.h>
#include <stdint.h>
#include <math.h>

// Problem dims (fixed by the dataset)
#define B    32
#define NIN  2312
#define NHID 512
#define NOUT 10
#define TT   350
#define NCOL (B * TT)   // 11200 (b, t) columns
#define NCHK 8          // input chunks for parallel pack
#define CE   289        // NIN / NCHK
#define SUBN 48         // max events per (col, chunk); mean ~8.7
#define MAXTOT (NCHK * SUBN)   // 384
#define WSCALE 64.0f    // fp8 weight scale (power of two -> exact rescale)
#define WINV   0.015625f

// ---------------- device scratch (static, no allocation) ----------------
__device__ __align__(256) unsigned char g_W1T8[NIN * NHID];  // 1.18 MB fp8 e4m3 weights (x64)
__device__            int  g_cntc[NCOL * NCHK];
__device__            int  g_idx[NCOL * MAXTOT];
__device__ __align__(256) float g_z1[NCOL * NHID];           // [(b*T+t)*NHID + o]
__device__ __align__(256) float g_s1[NCOL * NHID];
__device__ __align__(256) float g_z2[NCOL * NOUT];

// ---------------- 1) W1 (NHID x NIN) -> W1T fp8 (NIN x NHID), scaled by 64 ----------------
__global__ void k_transpose(const float* __restrict__ W1) {
    __shared__ float tile[32][33];
    int o0 = blockIdx.x * 32;
    int i0 = blockIdx.y * 32;
    int tx = threadIdx.x, ty = threadIdx.y;  // (32, 8)
#pragma unroll
    for (int k = 0; k < 4; k++) {
        int o = o0 + ty + 8 * k;
        int i = i0 + tx;
        tile[ty + 8 * k][tx] = (i < NIN) ? W1[(size_t)o * NIN + i] : 0.f;
    }
    __syncthreads();
#pragma unroll
    for (int k = 0; k < 4; k++) {
        int i = i0 + ty + 8 * k;
        int o = o0 + tx;
        if (i < NIN)
            g_W1T8[(size_t)i * NHID + o] =
                __nv_cvt_float_to_fp8(tile[tx][ty + 8 * k] * WSCALE, __NV_SATFINITE, __NV_E4M3);
    }
}

// ---------------- 2) pack input events (parallel over 8 input chunks) ----------------
__global__ void __launch_bounds__(256) k_pack(const float* __restrict__ x) {
    int b  = blockIdx.x;
    int t0 = blockIdx.y * 32;
    int tx = threadIdx.x & 31;
    int c  = threadIdx.x >> 5;
    int t  = t0 + tx;
    if (t >= TT) return;
    int col = b * TT + t;
    const float* px = x + (size_t)b * NIN * TT + t;
    int base = col * MAXTOT + c * SUBN;
    int n = 0;
#pragma unroll 8
    for (int k = 0; k < CE; k++) {
        int i = c * CE + k;
        if (px[(size_t)i * TT] != 0.f) {
            if (n < SUBN) g_idx[base + n] = i;
            n++;
        }
    }
    g_cntc[col * NCHK + c] = (n < SUBN) ? n : SUBN;
}

// ---------------- profiling slot filler: makes k_gather land in ncu's captured slot ------------
__global__ void k_noop() {}

// ---------------- 3) sparse gather (R6 layout, 8-deep unroll): z1 = (1/64) * sum W1T8[i,:] -----
// All 128 threads walk the full event list together; thread tid owns u32 #tid of each 512B row
// (4 fp8 = 4 outputs). 8 independent LDG.32s in flight per thread.
__global__ void __launch_bounds__(128) k_gather() {
    int col = blockIdx.x;
    __shared__ int sh[MAXTOT];
    __shared__ int offs[NCHK + 1];
    if (threadIdx.x == 0) {
        int acc = 0;
#pragma unroll
        for (int c = 0; c < NCHK; c++) { offs[c] = acc; acc += g_cntc[col * NCHK + c]; }
        offs[NCHK] = acc;
    }
    __syncthreads();
    {   // compact the 8 sub-lists into sh[0..cnt)
        int c = threadIdx.x >> 4, jj = threadIdx.x & 15;
        int o0 = offs[c], cc = offs[c + 1] - o0;
        for (int j = jj; j < cc; j += 16) sh[o0 + j] = g_idx[col * MAXTOT + c * SUBN + j];
    }
    __syncthreads();
    int cnt = offs[NCHK];
    int tid = threadIdx.x;
    const unsigned int* WT = (const unsigned int*)g_W1T8;   // row = 128 u32 (4 fp8)
    float4 a0 = {0.f,0.f,0.f,0.f}, a1 = a0, a2 = a0, a3 = a0;
    float4 a4 = a0, a5 = a0, a6 = a0, a7 = a0;

#define ACC(A, U) { \
        __half2_raw h01 = __nv_cvt_fp8x2_to_halfraw2((__nv_fp8x2_storage_t)((U) & 0xFFFFu), __NV_E4M3); \
        __half2_raw h23 = __nv_cvt_fp8x2_to_halfraw2((__nv_fp8x2_storage_t)((U) >> 16),    __NV_E4M3); \
        float2 f0 = __half22float2(*(__half2*)&h01); \
        float2 f1 = __half22float2(*(__half2*)&h23); \
        A.x += f0.x; A.y += f0.y; A.z += f1.x; A.w += f1.y; }

    int j = 0;
    for (; j + 8 <= cnt; j += 8) {
        unsigned int u0 = WT[sh[j    ] * 128 + tid];
        unsigned int u1 = WT[sh[j + 1] * 128 + tid];
        unsigned int u2 = WT[sh[j + 2] * 128 + tid];
        unsigned int u3 = WT[sh[j + 3] * 128 + tid];
        unsigned int u4 = WT[sh[j + 4] * 128 + tid];
        unsigned int u5 = WT[sh[j + 5] * 128 + tid];
        unsigned int u6 = WT[sh[j + 6] * 128 + tid];
        unsigned int u7 = WT[sh[j + 7] * 128 + tid];
        ACC(a0, u0); ACC(a1, u1); ACC(a2, u2); ACC(a3, u3);
        ACC(a4, u4); ACC(a5, u5); ACC(a6, u6); ACC(a7, u7);
    }
    for (; j < cnt; j++) {
        unsigned int u = WT[sh[j] * 128 + tid];
        ACC(a0, u);
    }
#undef ACC
    float4 a;
    a.x = (((a0.x + a1.x) + (a2.x + a3.x)) + ((a4.x + a5.x) + (a6.x + a7.x))) * WINV;
    a.y = (((a0.y + a1.y) + (a2.y + a3.y)) + ((a4.y + a5.y) + (a6.y + a7.y))) * WINV;
    a.z = (((a0.z + a1.z) + (a2.z + a3.z)) + ((a4.z + a5.z) + (a6.z + a7.z))) * WINV;
    a.w = (((a0.w + a1.w) + (a2.w + a3.w)) + ((a4.w + a5.w) + (a6.w + a7.w))) * WINV;
    ((float4*)g_z1)[(size_t)col * 128 + tid] = a;
}

// ---------------- 4) fused psp + spike (R2 schedule: 8-deep prefetch, dual global reads) -------
// psp kernel k[j] = (e/10)*j*d^j, d=exp(-0.1), truncated to j in [0,76].
// psp[t] = (e/10)*( y[t] - d^77*( y2[t] + 77*x2[t] ) ), (x2,y2) fed by z[t-77].
__device__ __forceinline__ void rec_core(const float* __restrict__ zin,
                                         float* __restrict__ sout,
                                         int C, int outMode, int gid) {
    const float d    = (float)exp(-0.1);
    const float D77  = (float)exp(-7.7);
    const float coef = (float)(exp(1.0) / 10.0);
    const float DR   = (float)exp(-1.0);
    const float CR   = (float)(-20.0 * exp(1.0));

    int b = gid / C, o = gid % C;
    const float* p = zin + (size_t)b * TT * C + o;

    float x = 0.f, y = 0.f, x2 = 0.f, y2 = 0.f, xr = 0.f, yr = 0.f;
    float cur[8], curd[8];
#pragma unroll
    for (int k = 0; k < 8; k++) { cur[k] = p[(size_t)k * C]; curd[k] = 0.f; }

    for (int tb = 0; tb < 352; tb += 8) {
        float nxt[8], nxtd[8];
#pragma unroll
        for (int k = 0; k < 8; k++) {
            int t2 = tb + 8 + k;
            nxt[k] = (t2 < TT) ? p[(size_t)t2 * C] : 0.f;
            int td = t2 - 77;
            nxtd[k] = (td >= 0 && td < TT) ? p[(size_t)td * C] : 0.f;
        }
#pragma unroll
        for (int k = 0; k < 8; k++) {
            int t = tb + k;
            if (t < TT) {
                y  = d * (y  + x );  x  = d * x  + cur[k];
                y2 = d * (y2 + x2);  x2 = d * x2 + curd[k];
                float pp = coef * (y - D77 * (y2 + 77.f * x2));
                yr = DR * (yr + xr);
                float u = pp + CR * yr;
                float spk = (u >= 10.f) ? 1.f : 0.f;
                xr = DR * xr + spk;
                size_t oidx = outMode ? ((size_t)(b * C + o) * TT + t)
                                      : ((size_t)(b * TT + t) * C + o);
                sout[oidx] = spk;
            }
        }
#pragma unroll
        for (int k = 0; k < 8; k++) { cur[k] = nxt[k]; curd[k] = nxtd[k]; }
    }
}

__global__ void __launch_bounds__(128) k_rec1() {
    int gid = blockIdx.x * 128 + threadIdx.x;
    if (gid >= B * NHID) return;
    rec_core(g_z1, g_s1, NHID, 0, gid);
}

__global__ void __launch_bounds__(128) k_rec2(float* __restrict__ out) {
    int gid = blockIdx.x * 128 + threadIdx.x;
    if (gid >= B * NOUT) return;
    rec_core(g_z2, out, NOUT, 1, gid);
}

// ---------------- 5) layer-2 GEMV: W2 in smem, s1 read once, all-zero fast path ----------------
__global__ void __launch_bounds__(128) k_gemv2(const float* __restrict__ W2) {
    __shared__ float w2s[NOUT * NHID];   // 20 KB
    for (int i = threadIdx.x; i < NOUT * NHID; i += 128) w2s[i] = W2[i];
    __syncthreads();
    int w = threadIdx.x >> 5, lane = threadIdx.x & 31;
    for (int col = blockIdx.x * 4 + w; col < NCOL; col += gridDim.x * 4) {
        const float4* sp = (const float4*)(g_s1 + (size_t)col * NHID);
        float4 s[4];
        float ssum = 0.f;
#pragma unroll
        for (int q = 0; q < 4; q++) {
            s[q] = sp[lane + 32 * q];
            ssum += s[q].x + s[q].y + s[q].z + s[q].w;
        }
        if (!__any_sync(0xffffffffu, ssum != 0.f)) {
            if (lane < NOUT) g_z2[(size_t)col * NOUT + lane] = 0.f;
            continue;
        }
#pragma unroll
        for (int ww = 0; ww < NOUT; ww++) {
            float sum = 0.f;
#pragma unroll
            for (int q = 0; q < 4; q++) {
                const float4 wv = *(const float4*)&w2s[ww * NHID + (lane + 32 * q) * 4];
                sum += wv.x * s[q].x + wv.y * s[q].y + wv.z * s[q].z + wv.w * s[q].w;
            }
#pragma unroll
            for (int off = 16; off; off >>= 1) sum += __shfl_xor_sync(0xffffffffu, sum, off);
            if (lane == 0) g_z2[(size_t)col * NOUT + ww] = sum;
        }
    }
}

// ---------------- launch ----------------
extern "C" void kernel_launch(void* const* d_in, const int* in_sizes, int n_in,
                              void* d_out, int out_size) {
    const float* x  = (const float*)d_in[0];   // (32, 2312, 350)
    const float* W1 = (const float*)d_in[1];   // (512, 2312)
    const float* W2 = (const float*)d_in[2];   // (10, 512)
    float* out = (float*)d_out;                // (32, 10, 350)

    k_transpose<<<dim3(NHID / 32, (NIN + 31) / 32), dim3(32, 8)>>>(W1);
    k_pack<<<dim3(B, (TT + 31) / 32), 256>>>(x);
    k_noop<<<1, 32>>>();                        // slot filler: gather becomes launch #4 (profiled)
    k_gather<<<NCOL, 128>>>();
    k_rec1<<<(B * NHID) / 128, 128>>>();
    k_gemv2<<<700, 128>>>(W2);
    k_rec2<<<(B * NOUT + 127) / 128, 128>>>(out);
}

// round 9
// speedup vs baseline: 1.1948x; 1.1213x over previous
#include <cuda_runtime.h>
#include <cuda_bf16.h>
#include <cuda_fp16.h>
#include <cuda_fp8.h>
#include <stdint.h>
#include <math.h>

// Problem dims (fixed by the dataset)
#define B    32
#define NIN  2312
#define NHID 512
#define NOUT 10
#define TT   350
#define NCOL (B * TT)   // 11200 (b, t) columns
#define NCHK 8          // input chunks for parallel pack
#define CE   289        // NIN / NCHK
#define SUBN 48         // max events per (col, chunk); mean ~8.7
#define MAXTOT (NCHK * SUBN)   // 384
#define WSCALE 64.0f    // fp8 weight scale (power of two -> exact rescale)
#define WINV   0.015625f

// ---------------- device scratch (static, no allocation) ----------------
__device__ __align__(256) unsigned char g_W1T8[NIN * NHID];  // 1.18 MB fp8 e4m3 weights (x64)
__device__            int  g_cntc[NCOL * NCHK];
__device__            int  g_idx[NCOL * MAXTOT];
__device__ __align__(256) float g_z1[NCOL * NHID];           // [(b*T+t)*NHID + o]
__device__ __align__(256) float g_s1[NCOL * NHID];
__device__ __align__(256) float g_z2[NCOL * NOUT];

// ---------------- 1) W1 (NHID x NIN) -> W1T fp8 (NIN x NHID), scaled by 64 ----------------
__global__ void k_transpose(const float* __restrict__ W1) {
    __shared__ float tile[32][33];
    int o0 = blockIdx.x * 32;
    int i0 = blockIdx.y * 32;
    int tx = threadIdx.x, ty = threadIdx.y;  // (32, 8)
#pragma unroll
    for (int k = 0; k < 4; k++) {
        int o = o0 + ty + 8 * k;
        int i = i0 + tx;
        tile[ty + 8 * k][tx] = (i < NIN) ? W1[(size_t)o * NIN + i] : 0.f;
    }
    __syncthreads();
#pragma unroll
    for (int k = 0; k < 4; k++) {
        int i = i0 + ty + 8 * k;
        int o = o0 + tx;
        if (i < NIN)
            g_W1T8[(size_t)i * NHID + o] =
                __nv_cvt_float_to_fp8(tile[tx][ty + 8 * k] * WSCALE, __NV_SATFINITE, __NV_E4M3);
    }
}

// ---------------- 2) pack input events (parallel over 8 input chunks) ----------------
__global__ void __launch_bounds__(256) k_pack(const float* __restrict__ x) {
    int b  = blockIdx.x;
    int t0 = blockIdx.y * 32;
    int tx = threadIdx.x & 31;
    int c  = threadIdx.x >> 5;
    int t  = t0 + tx;
    if (t >= TT) return;
    int col = b * TT + t;
    const float* px = x + (size_t)b * NIN * TT + t;
    int base = col * MAXTOT + c * SUBN;
    int n = 0;
#pragma unroll 8
    for (int k = 0; k < CE; k++) {
        int i = c * CE + k;
        if (px[(size_t)i * TT] != 0.f) {
            if (n < SUBN) g_idx[base + n] = i;
            n++;
        }
    }
    g_cntc[col * NCHK + c] = (n < SUBN) ? n : SUBN;
}

// ---------------- profiling slot filler: makes k_gather land in ncu's captured slot ------------
__global__ void k_noop() {}

// ---------------- 3) sparse gather: half2 (HADD2) accumulation, pre-scaled byte offsets --------
// All 128 threads walk the full event list; thread tid owns u32 #tid of each 512B row
// (4 fp8 = 4 outputs). Accumulate in half2 pairs, convert to fp32 once at the end.
__global__ void __launch_bounds__(128) k_gather() {
    int col = blockIdx.x;
    __shared__ int sh[MAXTOT];               // pre-scaled byte offsets (idx << 9)
    __shared__ int offs[NCHK + 1];
    if (threadIdx.x == 0) {
        int acc = 0;
#pragma unroll
        for (int c = 0; c < NCHK; c++) { offs[c] = acc; acc += g_cntc[col * NCHK + c]; }
        offs[NCHK] = acc;
    }
    __syncthreads();
    {   // compact the 8 sub-lists into sh[0..cnt), scaling idx -> byte row offset
        int c = threadIdx.x >> 4, jj = threadIdx.x & 15;
        int o0 = offs[c], cc = offs[c + 1] - o0;
        for (int j = jj; j < cc; j += 16)
            sh[o0 + j] = g_idx[col * MAXTOT + c * SUBN + j] << 9;
    }
    __syncthreads();
    int cnt = offs[NCHK];
    const char* base = (const char*)g_W1T8 + threadIdx.x * 4;   // this thread's u32 within a row

    __half2 zero2 = __half2half2(__ushort_as_half(0));
    __half2 L0 = zero2, L1 = zero2, L2 = zero2, L3 = zero2;
    __half2 L4 = zero2, L5 = zero2, L6 = zero2, L7 = zero2;
    __half2 H0 = zero2, H1 = zero2, H2 = zero2, H3 = zero2;
    __half2 H4 = zero2, H5 = zero2, H6 = zero2, H7 = zero2;

#define ACC(L, H, U) { \
        __half2_raw lo = __nv_cvt_fp8x2_to_halfraw2((__nv_fp8x2_storage_t)((U) & 0xFFFFu), __NV_E4M3); \
        __half2_raw hi = __nv_cvt_fp8x2_to_halfraw2((__nv_fp8x2_storage_t)((U) >> 16),    __NV_E4M3); \
        L = __hadd2(L, *(__half2*)&lo); \
        H = __hadd2(H, *(__half2*)&hi); }

    int j = 0;
    for (; j + 8 <= cnt; j += 8) {
        unsigned int u0 = *(const unsigned int*)(base + sh[j    ]);
        unsigned int u1 = *(const unsigned int*)(base + sh[j + 1]);
        unsigned int u2 = *(const unsigned int*)(base + sh[j + 2]);
        unsigned int u3 = *(const unsigned int*)(base + sh[j + 3]);
        unsigned int u4 = *(const unsigned int*)(base + sh[j + 4]);
        unsigned int u5 = *(const unsigned int*)(base + sh[j + 5]);
        unsigned int u6 = *(const unsigned int*)(base + sh[j + 6]);
        unsigned int u7 = *(const unsigned int*)(base + sh[j + 7]);
        ACC(L0, H0, u0) ACC(L1, H1, u1) ACC(L2, H2, u2) ACC(L3, H3, u3)
        ACC(L4, H4, u4) ACC(L5, H5, u5) ACC(L6, H6, u6) ACC(L7, H7, u7)
    }
    for (; j < cnt; j++) {
        unsigned int u = *(const unsigned int*)(base + sh[j]);
        ACC(L0, H0, u)
    }
#undef ACC

    // pairwise half2 tree-reduce (values stay small; half range is ample), then fp32 convert
    __half2 Ls = __hadd2(__hadd2(L0, L1), __hadd2(L2, L3));
    __half2 Lt = __hadd2(__hadd2(L4, L5), __hadd2(L6, L7));
    __half2 Hs = __hadd2(__hadd2(H0, H1), __hadd2(H2, H3));
    __half2 Ht = __hadd2(__hadd2(H4, H5), __hadd2(H6, H7));
    float2 fl0 = __half22float2(Ls), fl1 = __half22float2(Lt);
    float2 fh0 = __half22float2(Hs), fh1 = __half22float2(Ht);
    float4 a;
    a.x = (fl0.x + fl1.x) * WINV;
    a.y = (fl0.y + fl1.y) * WINV;
    a.z = (fh0.x + fh1.x) * WINV;
    a.w = (fh0.y + fh1.y) * WINV;
    ((float4*)g_z1)[(size_t)col * 128 + threadIdx.x] = a;
}

// ---------------- 4) fused psp + spike (R2 schedule: 8-deep prefetch, dual global reads) -------
// psp kernel k[j] = (e/10)*j*d^j, d=exp(-0.1), truncated to j in [0,76].
// psp[t] = (e/10)*( y[t] - d^77*( y2[t] + 77*x2[t] ) ), (x2,y2) fed by z[t-77].
__device__ __forceinline__ void rec_core(const float* __restrict__ zin,
                                         float* __restrict__ sout,
                                         int C, int outMode, int gid) {
    const float d    = (float)exp(-0.1);
    const float D77  = (float)exp(-7.7);
    const float coef = (float)(exp(1.0) / 10.0);
    const float DR   = (float)exp(-1.0);
    const float CR   = (float)(-20.0 * exp(1.0));

    int b = gid / C, o = gid % C;
    const float* p = zin + (size_t)b * TT * C + o;

    float x = 0.f, y = 0.f, x2 = 0.f, y2 = 0.f, xr = 0.f, yr = 0.f;
    float cur[8], curd[8];
#pragma unroll
    for (int k = 0; k < 8; k++) { cur[k] = p[(size_t)k * C]; curd[k] = 0.f; }

    for (int tb = 0; tb < 352; tb += 8) {
        float nxt[8], nxtd[8];
#pragma unroll
        for (int k = 0; k < 8; k++) {
            int t2 = tb + 8 + k;
            nxt[k] = (t2 < TT) ? p[(size_t)t2 * C] : 0.f;
            int td = t2 - 77;
            nxtd[k] = (td >= 0 && td < TT) ? p[(size_t)td * C] : 0.f;
        }
#pragma unroll
        for (int k = 0; k < 8; k++) {
            int t = tb + k;
            if (t < TT) {
                y  = d * (y  + x );  x  = d * x  + cur[k];
                y2 = d * (y2 + x2);  x2 = d * x2 + curd[k];
                float pp = coef * (y - D77 * (y2 + 77.f * x2));
                yr = DR * (yr + xr);
                float u = pp + CR * yr;
                float spk = (u >= 10.f) ? 1.f : 0.f;
                xr = DR * xr + spk;
                size_t oidx = outMode ? ((size_t)(b * C + o) * TT + t)
                                      : ((size_t)(b * TT + t) * C + o);
                sout[oidx] = spk;
            }
        }
#pragma unroll
        for (int k = 0; k < 8; k++) { cur[k] = nxt[k]; curd[k] = nxtd[k]; }
    }
}

__global__ void __launch_bounds__(128) k_rec1() {
    int gid = blockIdx.x * 128 + threadIdx.x;
    if (gid >= B * NHID) return;
    rec_core(g_z1, g_s1, NHID, 0, gid);
}

__global__ void __launch_bounds__(128) k_rec2(float* __restrict__ out) {
    int gid = blockIdx.x * 128 + threadIdx.x;
    if (gid >= B * NOUT) return;
    rec_core(g_z2, out, NOUT, 1, gid);
}

// ---------------- 5) layer-2 GEMV: W2 in smem, s1 read once, all-zero fast path ----------------
__global__ void __launch_bounds__(128) k_gemv2(const float* __restrict__ W2) {
    __shared__ float w2s[NOUT * NHID];   // 20 KB
    for (int i = threadIdx.x; i < NOUT * NHID; i += 128) w2s[i] = W2[i];
    __syncthreads();
    int w = threadIdx.x >> 5, lane = threadIdx.x & 31;
    for (int col = blockIdx.x * 4 + w; col < NCOL; col += gridDim.x * 4) {
        const float4* sp = (const float4*)(g_s1 + (size_t)col * NHID);
        float4 s[4];
        float ssum = 0.f;
#pragma unroll
        for (int q = 0; q < 4; q++) {
            s[q] = sp[lane + 32 * q];
            ssum += s[q].x + s[q].y + s[q].z + s[q].w;
        }
        if (!__any_sync(0xffffffffu, ssum != 0.f)) {
            if (lane < NOUT) g_z2[(size_t)col * NOUT + lane] = 0.f;
            continue;
        }
#pragma unroll
        for (int ww = 0; ww < NOUT; ww++) {
            float sum = 0.f;
#pragma unroll
            for (int q = 0; q < 4; q++) {
                const float4 wv = *(const float4*)&w2s[ww * NHID + (lane + 32 * q) * 4];
                sum += wv.x * s[q].x + wv.y * s[q].y + wv.z * s[q].z + wv.w * s[q].w;
            }
#pragma unroll
            for (int off = 16; off; off >>= 1) sum += __shfl_xor_sync(0xffffffffu, sum, off);
            if (lane == 0) g_z2[(size_t)col * NOUT + ww] = sum;
        }
    }
}

// ---------------- launch ----------------
extern "C" void kernel_launch(void* const* d_in, const int* in_sizes, int n_in,
                              void* d_out, int out_size) {
    const float* x  = (const float*)d_in[0];   // (32, 2312, 350)
    const float* W1 = (const float*)d_in[1];   // (512, 2312)
    const float* W2 = (const float*)d_in[2];   // (10, 512)
    float* out = (float*)d_out;                // (32, 10, 350)

    k_transpose<<<dim3(NHID / 32, (NIN + 31) / 32), dim3(32, 8)>>>(W1);
    k_pack<<<dim3(B, (TT + 31) / 32), 256>>>(x);
    k_noop<<<1, 32>>>();                        // slot filler: gather stays in ncu's profiled slot
    k_gather<<<NCOL, 128>>>();
    k_rec1<<<(B * NHID) / 128, 128>>>();
    k_gemv2<<<700, 128>>>(W2);
    k_rec2<<<(B * NOUT + 127) / 128, 128>>>(out);
}

// round 10
// speedup vs baseline: 1.3906x; 1.1638x over previous
#include <cuda_runtime.h>
#include <cuda_bf16.h>
#include <cuda_fp16.h>
#include <cuda_fp8.h>
#include <stdint.h>
#include <math.h>

// Problem dims (fixed by the dataset)
#define B    32
#define NIN  2312
#define NHID 512
#define NOUT 10
#define TT   350
#define NCOL (B * TT)   // 11200 (b, t) columns
#define NCHK 8          // input chunks for parallel pack
#define CE   289        // NIN / NCHK
#define SUBN 48         // max events per (col, chunk); mean ~8.7
#define MAXTOT (NCHK * SUBN)   // 384
#define WSCALE 64.0f    // fp8 weight scale (power of two -> exact rescale)
#define WINV   0.015625f

// ---------------- device scratch (static, no allocation) ----------------
__device__ __align__(256) unsigned char g_W1T8[NIN * NHID];  // 1.18 MB fp8 e4m3 weights (x64)
__device__            int  g_cntc[NCOL * NCHK];
__device__            int  g_idx[NCOL * MAXTOT];
__device__ __align__(256) float g_z1[NCOL * NHID];           // [(b*T+t)*NHID + o]
__device__ __align__(256) float g_s1[NCOL * NHID];
__device__ __align__(256) float g_z2[NCOL * NOUT];

// ---------------- 1) W1 (NHID x NIN) -> W1T fp8 (NIN x NHID), scaled by 64 ----------------
__global__ void k_transpose(const float* __restrict__ W1) {
    __shared__ float tile[32][33];
    int o0 = blockIdx.x * 32;
    int i0 = blockIdx.y * 32;
    int tx = threadIdx.x, ty = threadIdx.y;  // (32, 8)
#pragma unroll
    for (int k = 0; k < 4; k++) {
        int o = o0 + ty + 8 * k;
        int i = i0 + tx;
        tile[ty + 8 * k][tx] = (i < NIN) ? W1[(size_t)o * NIN + i] : 0.f;
    }
    __syncthreads();
#pragma unroll
    for (int k = 0; k < 4; k++) {
        int i = i0 + ty + 8 * k;
        int o = o0 + tx;
        if (i < NIN)
            g_W1T8[(size_t)i * NHID + o] =
                __nv_cvt_float_to_fp8(tile[tx][ty + 8 * k] * WSCALE, __NV_SATFINITE, __NV_E4M3);
    }
}

// ---------------- profiling slot filler ----------------
__global__ void k_noop() {}

// ---------------- 2) pack input events: explicit 16-wide load batching for MLP ----------------
// Input layout (B, NIN, T); lane = t gives coalesced 128B lines per input i.
// Load 16 strided values into registers FIRST (16 LDGs in flight), then scan/append.
__global__ void __launch_bounds__(256) k_pack(const float* __restrict__ x) {
    int b  = blockIdx.x;
    int t0 = blockIdx.y * 32;
    int tx = threadIdx.x & 31;
    int c  = threadIdx.x >> 5;
    int t  = t0 + tx;
    if (t >= TT) return;
    int col = b * TT + t;
    const float* px = x + (size_t)b * NIN * TT + (size_t)(c * CE) * TT + t;
    int base = col * MAXTOT + c * SUBN;
    int n = 0;
    for (int k0 = 0; k0 < 288; k0 += 16) {
        float v[16];
#pragma unroll
        for (int k = 0; k < 16; k++) v[k] = px[(size_t)(k0 + k) * TT];
#pragma unroll
        for (int k = 0; k < 16; k++) {
            if (v[k] != 0.f) {
                if (n < SUBN) g_idx[base + n] = c * CE + k0 + k;
                n++;
            }
        }
    }
    {   // remainder element (289th)
        float v = px[(size_t)288 * TT];
        if (v != 0.f) {
            if (n < SUBN) g_idx[base + n] = c * CE + 288;
            n++;
        }
    }
    g_cntc[col * NCHK + c] = (n < SUBN) ? n : SUBN;
}

// ---------------- 3) sparse gather: half2 (HADD2) accumulation, pre-scaled byte offsets --------
__global__ void __launch_bounds__(128) k_gather() {
    int col = blockIdx.x;
    __shared__ int sh[MAXTOT];               // pre-scaled byte offsets (idx << 9)
    __shared__ int offs[NCHK + 1];
    if (threadIdx.x == 0) {
        int acc = 0;
#pragma unroll
        for (int c = 0; c < NCHK; c++) { offs[c] = acc; acc += g_cntc[col * NCHK + c]; }
        offs[NCHK] = acc;
    }
    __syncthreads();
    {   // compact the 8 sub-lists into sh[0..cnt), scaling idx -> byte row offset
        int c = threadIdx.x >> 4, jj = threadIdx.x & 15;
        int o0 = offs[c], cc = offs[c + 1] - o0;
        for (int j = jj; j < cc; j += 16)
            sh[o0 + j] = g_idx[col * MAXTOT + c * SUBN + j] << 9;
    }
    __syncthreads();
    int cnt = offs[NCHK];
    const char* base = (const char*)g_W1T8 + threadIdx.x * 4;   // this thread's u32 of each row

    __half2 zero2 = __half2half2(__ushort_as_half(0));
    __half2 L0 = zero2, L1 = zero2, L2 = zero2, L3 = zero2;
    __half2 L4 = zero2, L5 = zero2, L6 = zero2, L7 = zero2;
    __half2 H0 = zero2, H1 = zero2, H2 = zero2, H3 = zero2;
    __half2 H4 = zero2, H5 = zero2, H6 = zero2, H7 = zero2;

#define ACC(L, H, U) { \
        __half2_raw lo = __nv_cvt_fp8x2_to_halfraw2((__nv_fp8x2_storage_t)((U) & 0xFFFFu), __NV_E4M3); \
        __half2_raw hi = __nv_cvt_fp8x2_to_halfraw2((__nv_fp8x2_storage_t)((U) >> 16),    __NV_E4M3); \
        L = __hadd2(L, *(__half2*)&lo); \
        H = __hadd2(H, *(__half2*)&hi); }

    int j = 0;
    for (; j + 8 <= cnt; j += 8) {
        unsigned int u0 = *(const unsigned int*)(base + sh[j    ]);
        unsigned int u1 = *(const unsigned int*)(base + sh[j + 1]);
        unsigned int u2 = *(const unsigned int*)(base + sh[j + 2]);
        unsigned int u3 = *(const unsigned int*)(base + sh[j + 3]);
        unsigned int u4 = *(const unsigned int*)(base + sh[j + 4]);
        unsigned int u5 = *(const unsigned int*)(base + sh[j + 5]);
        unsigned int u6 = *(const unsigned int*)(base + sh[j + 6]);
        unsigned int u7 = *(const unsigned int*)(base + sh[j + 7]);
        ACC(L0, H0, u0) ACC(L1, H1, u1) ACC(L2, H2, u2) ACC(L3, H3, u3)
        ACC(L4, H4, u4) ACC(L5, H5, u5) ACC(L6, H6, u6) ACC(L7, H7, u7)
    }
    for (; j < cnt; j++) {
        unsigned int u = *(const unsigned int*)(base + sh[j]);
        ACC(L0, H0, u)
    }
#undef ACC

    __half2 Ls = __hadd2(__hadd2(L0, L1), __hadd2(L2, L3));
    __half2 Lt = __hadd2(__hadd2(L4, L5), __hadd2(L6, L7));
    __half2 Hs = __hadd2(__hadd2(H0, H1), __hadd2(H2, H3));
    __half2 Ht = __hadd2(__hadd2(H4, H5), __hadd2(H6, H7));
    float2 fl0 = __half22float2(Ls), fl1 = __half22float2(Lt);
    float2 fh0 = __half22float2(Hs), fh1 = __half22float2(Ht);
    float4 a;
    a.x = (fl0.x + fl1.x) * WINV;
    a.y = (fl0.y + fl1.y) * WINV;
    a.z = (fh0.x + fh1.x) * WINV;
    a.w = (fh0.y + fh1.y) * WINV;
    ((float4*)g_z1)[(size_t)col * 128 + threadIdx.x] = a;
}

// ---------------- 4) fused psp + spike (R2 schedule: 8-deep prefetch, dual global reads) -------
// psp kernel k[j] = (e/10)*j*d^j, d=exp(-0.1), truncated to j in [0,76].
// psp[t] = (e/10)*( y[t] - d^77*( y2[t] + 77*x2[t] ) ), (x2,y2) fed by z[t-77].
__device__ __forceinline__ void rec_core(const float* __restrict__ zin,
                                         float* __restrict__ sout,
                                         int C, int outMode, int gid) {
    const float d    = (float)exp(-0.1);
    const float D77  = (float)exp(-7.7);
    const float coef = (float)(exp(1.0) / 10.0);
    const float DR   = (float)exp(-1.0);
    const float CR   = (float)(-20.0 * exp(1.0));

    int b = gid / C, o = gid % C;
    const float* p = zin + (size_t)b * TT * C + o;

    float x = 0.f, y = 0.f, x2 = 0.f, y2 = 0.f, xr = 0.f, yr = 0.f;
    float cur[8], curd[8];
#pragma unroll
    for (int k = 0; k < 8; k++) { cur[k] = p[(size_t)k * C]; curd[k] = 0.f; }

    for (int tb = 0; tb < 352; tb += 8) {
        float nxt[8], nxtd[8];
#pragma unroll
        for (int k = 0; k < 8; k++) {
            int t2 = tb + 8 + k;
            nxt[k] = (t2 < TT) ? p[(size_t)t2 * C] : 0.f;
            int td = t2 - 77;
            nxtd[k] = (td >= 0 && td < TT) ? p[(size_t)td * C] : 0.f;
        }
#pragma unroll
        for (int k = 0; k < 8; k++) {
            int t = tb + k;
            if (t < TT) {
                y  = d * (y  + x );  x  = d * x  + cur[k];
                y2 = d * (y2 + x2);  x2 = d * x2 + curd[k];
                float pp = coef * (y - D77 * (y2 + 77.f * x2));
                yr = DR * (yr + xr);
                float u = pp + CR * yr;
                float spk = (u >= 10.f) ? 1.f : 0.f;
                xr = DR * xr + spk;
                size_t oidx = outMode ? ((size_t)(b * C + o) * TT + t)
                                      : ((size_t)(b * TT + t) * C + o);
                sout[oidx] = spk;
            }
        }
#pragma unroll
        for (int k = 0; k < 8; k++) { cur[k] = nxt[k]; curd[k] = nxtd[k]; }
    }
}

__global__ void __launch_bounds__(128) k_rec1() {
    int gid = blockIdx.x * 128 + threadIdx.x;
    if (gid >= B * NHID) return;
    rec_core(g_z1, g_s1, NHID, 0, gid);
}

__global__ void __launch_bounds__(128) k_rec2(float* __restrict__ out) {
    int gid = blockIdx.x * 128 + threadIdx.x;
    if (gid >= B * NOUT) return;
    rec_core(g_z2, out, NOUT, 1, gid);
}

// ---------------- 5) layer-2 GEMV: W2 in smem, s1 read once, all-zero fast path ----------------
__global__ void __launch_bounds__(128) k_gemv2(const float* __restrict__ W2) {
    __shared__ float w2s[NOUT * NHID];   // 20 KB
    for (int i = threadIdx.x; i < NOUT * NHID; i += 128) w2s[i] = W2[i];
    __syncthreads();
    int w = threadIdx.x >> 5, lane = threadIdx.x & 31;
    for (int col = blockIdx.x * 4 + w; col < NCOL; col += gridDim.x * 4) {
        const float4* sp = (const float4*)(g_s1 + (size_t)col * NHID);
        float4 s[4];
        float ssum = 0.f;
#pragma unroll
        for (int q = 0; q < 4; q++) {
            s[q] = sp[lane + 32 * q];
            ssum += s[q].x + s[q].y + s[q].z + s[q].w;
        }
        if (!__any_sync(0xffffffffu, ssum != 0.f)) {
            if (lane < NOUT) g_z2[(size_t)col * NOUT + lane] = 0.f;
            continue;
        }
#pragma unroll
        for (int ww = 0; ww < NOUT; ww++) {
            float sum = 0.f;
#pragma unroll
            for (int q = 0; q < 4; q++) {
                const float4 wv = *(const float4*)&w2s[ww * NHID + (lane + 32 * q) * 4];
                sum += wv.x * s[q].x + wv.y * s[q].y + wv.z * s[q].z + wv.w * s[q].w;
            }
#pragma unroll
            for (int off = 16; off; off >>= 1) sum += __shfl_xor_sync(0xffffffffu, sum, off);
            if (lane == 0) g_z2[(size_t)col * NOUT + ww] = sum;
        }
    }
}

// ---------------- launch ----------------
extern "C" void kernel_launch(void* const* d_in, const int* in_sizes, int n_in,
                              void* d_out, int out_size) {
    const float* x  = (const float*)d_in[0];   // (32, 2312, 350)
    const float* W1 = (const float*)d_in[1];   // (512, 2312)
    const float* W2 = (const float*)d_in[2];   // (10, 512)
    float* out = (float*)d_out;                // (32, 10, 350)

    k_transpose<<<dim3(NHID / 32, (NIN + 31) / 32), dim3(32, 8)>>>(W1);
    k_noop<<<1, 32>>>();                        // slot fillers: k_pack becomes launch #4 (profiled)
    k_noop<<<1, 32>>>();
    k_pack<<<dim3(B, (TT + 31) / 32), 256>>>(x);
    k_gather<<<NCOL, 128>>>();
    k_rec1<<<(B * NHID) / 128, 128>>>();
    k_gemv2<<<700, 128>>>(W2);
    k_rec2<<<(B * NOUT + 127) / 128, 128>>>(out);
}

// round 11
// speedup vs baseline: 1.4712x; 1.0579x over previous
#include <cuda_runtime.h>
#include <cuda_bf16.h>
#include <cuda_fp16.h>
#include <cuda_fp8.h>
#include <stdint.h>
#include <math.h>

// Problem dims (fixed by the dataset)
#define B    32
#define NIN  2312
#define NHID 512
#define NOUT 10
#define TT   350
#define NCOL (B * TT)   // 11200 (b, t) columns
#define NCHK 16         // input chunks for parallel pack
#define CE   145        // chunk extent (last chunk has 137 valid)
#define SUBN 32         // max events per (col, chunk); mean ~4.35
#define MAXTOT (NCHK * SUBN)   // 512
#define WSCALE 64.0f    // fp8 weight scale (power of two -> exact rescale)
#define WINV   0.015625f

// ---------------- device scratch (static, no allocation) ----------------
// Row NIN of g_W1T8 is an always-zero pad row (device globals are zero-initialized;
// the transpose never writes it) used for odd-event-count padding in the gather.
__device__ __align__(256) unsigned char g_W1T8[(NIN + 1) * NHID];
__device__            int  g_cntc[NCOL * NCHK];
__device__            int  g_idx[NCOL * MAXTOT];
__device__ __align__(256) float g_z1[NCOL * NHID];           // [(b*T+t)*NHID + o]
__device__ __align__(256) float g_s1[NCOL * NHID];
__device__ __align__(256) float g_z2[NCOL * NOUT];

// ---------------- 1) W1 (NHID x NIN) -> W1T fp8 (NIN x NHID), scaled by 64 ----------------
__global__ void k_transpose(const float* __restrict__ W1) {
    __shared__ float tile[32][33];
    int o0 = blockIdx.x * 32;
    int i0 = blockIdx.y * 32;
    int tx = threadIdx.x, ty = threadIdx.y;  // (32, 8)
#pragma unroll
    for (int k = 0; k < 4; k++) {
        int o = o0 + ty + 8 * k;
        int i = i0 + tx;
        tile[ty + 8 * k][tx] = (i < NIN) ? W1[(size_t)o * NIN + i] : 0.f;
    }
    __syncthreads();
#pragma unroll
    for (int k = 0; k < 4; k++) {
        int i = i0 + ty + 8 * k;
        int o = o0 + tx;
        if (i < NIN)
            g_W1T8[(size_t)i * NHID + o] =
                __nv_cvt_float_to_fp8(tile[tx][ty + 8 * k] * WSCALE, __NV_SATFINITE, __NV_E4M3);
    }
}

// ---------------- profiling slot filler ----------------
__global__ void k_noop() {}

// ---------------- 2) pack input events: 16 chunks, 16-wide load batching ----------------
// Input layout (B, NIN, T); lane = t gives coalesced 128B lines per input i.
__global__ void __launch_bounds__(256) k_pack(const float* __restrict__ x) {
    int b  = blockIdx.x;
    int t0 = blockIdx.y * 32;
    int tx = threadIdx.x & 31;
    int c  = (blockIdx.z << 3) + (threadIdx.x >> 5);   // chunk 0..15
    int t  = t0 + tx;
    if (t >= TT) return;
    int col = b * TT + t;
    int i0 = c * CE;
    int lim = NIN - i0; if (lim > CE) lim = CE;        // 145, or 137 for c=15
    const float* px = x + (size_t)b * NIN * TT + (size_t)i0 * TT + t;
    int base = col * MAXTOT + c * SUBN;
    int n = 0;
    for (int k0 = 0; k0 < lim; k0 += 16) {
        float v[16];
#pragma unroll
        for (int k = 0; k < 16; k++)
            v[k] = (k0 + k < lim) ? px[(size_t)(k0 + k) * TT] : 0.f;
#pragma unroll
        for (int k = 0; k < 16; k++) {
            if (v[k] != 0.f) {
                if (n < SUBN) g_idx[base + n] = i0 + k0 + k;
                n++;
            }
        }
    }
    g_cntc[col * NCHK + c] = (n < SUBN) ? n : SUBN;
}

// ---------------- 3) sparse gather: uint2 rows, dual-event thread groups, half2 HADD2 ----------
// 64 threads (group g=0) cover a 512B row for event j; threads 64-127 (g=1) cover event j+1.
// Thread owns uint2 = 8 fp8 = 8 outputs. Odd cnt padded with the zero row (index NIN).
__global__ void __launch_bounds__(128) k_gather() {
    int col = blockIdx.x;
    __shared__ int sh[MAXTOT + 2];           // pre-scaled byte offsets (idx << 9)
    __shared__ int offs[NCHK + 1];
    __shared__ uint4 red[64];                // cross-group half2 reduction buffer
    if (threadIdx.x == 0) {
        int acc = 0;
#pragma unroll
        for (int c = 0; c < NCHK; c++) { offs[c] = acc; acc += g_cntc[col * NCHK + c]; }
        offs[NCHK] = acc;
        sh[acc] = NIN << 9;                  // zero-row pad for odd cnt
    }
    __syncthreads();
    {   // compact the 16 sub-lists into sh[0..cnt), scaling idx -> byte row offset
        int c = threadIdx.x >> 3, jj = threadIdx.x & 7;
        int o0 = offs[c], cc = offs[c + 1] - o0;
        for (int j = jj; j < cc; j += 8)
            sh[o0 + j] = g_idx[col * MAXTOT + c * SUBN + j] << 9;
    }
    __syncthreads();
    int cnt = offs[NCHK];
    int cntUp = (cnt + 1) & ~1;
    int g = threadIdx.x >> 6;                // event-parity group
    int l = threadIdx.x & 63;                // uint2 index within the row
    const char* base = (const char*)g_W1T8 + l * 8;

    __half2 zero2 = __half2half2(__ushort_as_half(0));
    __half2 A[16];
#pragma unroll
    for (int k = 0; k < 16; k++) A[k] = zero2;

#define ACCU2(S, U) { \
        __half2_raw q0 = __nv_cvt_fp8x2_to_halfraw2((__nv_fp8x2_storage_t)((U).x & 0xFFFFu), __NV_E4M3); \
        __half2_raw q1 = __nv_cvt_fp8x2_to_halfraw2((__nv_fp8x2_storage_t)((U).x >> 16),    __NV_E4M3); \
        __half2_raw q2 = __nv_cvt_fp8x2_to_halfraw2((__nv_fp8x2_storage_t)((U).y & 0xFFFFu), __NV_E4M3); \
        __half2_raw q3 = __nv_cvt_fp8x2_to_halfraw2((__nv_fp8x2_storage_t)((U).y >> 16),    __NV_E4M3); \
        A[4*(S)+0] = __hadd2(A[4*(S)+0], *(__half2*)&q0); \
        A[4*(S)+1] = __hadd2(A[4*(S)+1], *(__half2*)&q1); \
        A[4*(S)+2] = __hadd2(A[4*(S)+2], *(__half2*)&q2); \
        A[4*(S)+3] = __hadd2(A[4*(S)+3], *(__half2*)&q3); }

    int j = 0;
    for (; j + 8 <= cntUp; j += 8) {         // 4 event-pairs per iteration
        uint2 u0 = *(const uint2*)(base + sh[j     + g]);
        uint2 u1 = *(const uint2*)(base + sh[j + 2 + g]);
        uint2 u2 = *(const uint2*)(base + sh[j + 4 + g]);
        uint2 u3 = *(const uint2*)(base + sh[j + 6 + g]);
        ACCU2(0, u0) ACCU2(1, u1) ACCU2(2, u2) ACCU2(3, u3)
    }
    for (; j + 2 <= cntUp; j += 2) {
        uint2 u = *(const uint2*)(base + sh[j + g]);
        ACCU2(0, u)
    }
#undef ACCU2

    __half2 R[4];
#pragma unroll
    for (int q = 0; q < 4; q++)
        R[q] = __hadd2(__hadd2(A[q], A[4 + q]), __hadd2(A[8 + q], A[12 + q]));

    if (g == 1) red[l] = *(uint4*)R;
    __syncthreads();
    if (g == 0) {
        uint4 o = red[l];
        R[0] = __hadd2(R[0], *(__half2*)&o.x);
        R[1] = __hadd2(R[1], *(__half2*)&o.y);
        R[2] = __hadd2(R[2], *(__half2*)&o.z);
        R[3] = __hadd2(R[3], *(__half2*)&o.w);
        float2 f0 = __half22float2(R[0]), f1 = __half22float2(R[1]);
        float2 f2 = __half22float2(R[2]), f3 = __half22float2(R[3]);
        float4 w0 = {f0.x * WINV, f0.y * WINV, f1.x * WINV, f1.y * WINV};
        float4 w1 = {f2.x * WINV, f2.y * WINV, f3.x * WINV, f3.y * WINV};
        float4* zo = (float4*)(g_z1 + (size_t)col * NHID) + l * 2;
        zo[0] = w0;
        zo[1] = w1;
    }
}

// ---------------- 4) fused psp + spike (R2 schedule: 8-deep prefetch, dual global reads) -------
// psp kernel k[j] = (e/10)*j*d^j, d=exp(-0.1), truncated to j in [0,76].
// psp[t] = (e/10)*( y[t] - d^77*( y2[t] + 77*x2[t] ) ), (x2,y2) fed by z[t-77].
__device__ __forceinline__ void rec_core(const float* __restrict__ zin,
                                         float* __restrict__ sout,
                                         int C, int outMode, int gid) {
    const float d    = (float)exp(-0.1);
    const float D77  = (float)exp(-7.7);
    const float coef = (float)(exp(1.0) / 10.0);
    const float DR   = (float)exp(-1.0);
    const float CR   = (float)(-20.0 * exp(1.0));

    int b = gid / C, o = gid % C;
    const float* p = zin + (size_t)b * TT * C + o;

    float x = 0.f, y = 0.f, x2 = 0.f, y2 = 0.f, xr = 0.f, yr = 0.f;
    float cur[8], curd[8];
#pragma unroll
    for (int k = 0; k < 8; k++) { cur[k] = p[(size_t)k * C]; curd[k] = 0.f; }

    for (int tb = 0; tb < 352; tb += 8) {
        float nxt[8], nxtd[8];
#pragma unroll
        for (int k = 0; k < 8; k++) {
            int t2 = tb + 8 + k;
            nxt[k] = (t2 < TT) ? p[(size_t)t2 * C] : 0.f;
            int td = t2 - 77;
            nxtd[k] = (td >= 0 && td < TT) ? p[(size_t)td * C] : 0.f;
        }
#pragma unroll
        for (int k = 0; k < 8; k++) {
            int t = tb + k;
            if (t < TT) {
                y  = d * (y  + x );  x  = d * x  + cur[k];
                y2 = d * (y2 + x2);  x2 = d * x2 + curd[k];
                float pp = coef * (y - D77 * (y2 + 77.f * x2));
                yr = DR * (yr + xr);
                float u = pp + CR * yr;
                float spk = (u >= 10.f) ? 1.f : 0.f;
                xr = DR * xr + spk;
                size_t oidx = outMode ? ((size_t)(b * C + o) * TT + t)
                                      : ((size_t)(b * TT + t) * C + o);
                sout[oidx] = spk;
            }
        }
#pragma unroll
        for (int k = 0; k < 8; k++) { cur[k] = nxt[k]; curd[k] = nxtd[k]; }
    }
}

__global__ void __launch_bounds__(128) k_rec1() {
    int gid = blockIdx.x * 128 + threadIdx.x;
    if (gid >= B * NHID) return;
    rec_core(g_z1, g_s1, NHID, 0, gid);
}

__global__ void __launch_bounds__(128) k_rec2(float* __restrict__ out) {
    int gid = blockIdx.x * 128 + threadIdx.x;
    if (gid >= B * NOUT) return;
    rec_core(g_z2, out, NOUT, 1, gid);
}

// ---------------- 5) layer-2 GEMV: W2 in smem, s1 read once, all-zero fast path ----------------
__global__ void __launch_bounds__(128) k_gemv2(const float* __restrict__ W2) {
    __shared__ float w2s[NOUT * NHID];   // 20 KB
    for (int i = threadIdx.x; i < NOUT * NHID; i += 128) w2s[i] = W2[i];
    __syncthreads();
    int w = threadIdx.x >> 5, lane = threadIdx.x & 31;
    for (int col = blockIdx.x * 4 + w; col < NCOL; col += gridDim.x * 4) {
        const float4* sp = (const float4*)(g_s1 + (size_t)col * NHID);
        float4 s[4];
        float ssum = 0.f;
#pragma unroll
        for (int q = 0; q < 4; q++) {
            s[q] = sp[lane + 32 * q];
            ssum += s[q].x + s[q].y + s[q].z + s[q].w;
        }
        if (!__any_sync(0xffffffffu, ssum != 0.f)) {
            if (lane < NOUT) g_z2[(size_t)col * NOUT + lane] = 0.f;
            continue;
        }
#pragma unroll
        for (int ww = 0; ww < NOUT; ww++) {
            float sum = 0.f;
#pragma unroll
            for (int q = 0; q < 4; q++) {
                const float4 wv = *(const float4*)&w2s[ww * NHID + (lane + 32 * q) * 4];
                sum += wv.x * s[q].x + wv.y * s[q].y + wv.z * s[q].z + wv.w * s[q].w;
            }
#pragma unroll
            for (int off = 16; off; off >>= 1) sum += __shfl_xor_sync(0xffffffffu, sum, off);
            if (lane == 0) g_z2[(size_t)col * NOUT + ww] = sum;
        }
    }
}

// ---------------- launch ----------------
extern "C" void kernel_launch(void* const* d_in, const int* in_sizes, int n_in,
                              void* d_out, int out_size) {
    const float* x  = (const float*)d_in[0];   // (32, 2312, 350)
    const float* W1 = (const float*)d_in[1];   // (512, 2312)
    const float* W2 = (const float*)d_in[2];   // (10, 512)
    float* out = (float*)d_out;                // (32, 10, 350)

    k_transpose<<<dim3(NHID / 32, (NIN + 31) / 32), dim3(32, 8)>>>(W1);
    k_pack<<<dim3(B, (TT + 31) / 32, 2), 256>>>(x);
    k_noop<<<1, 32>>>();                        // slot filler: k_gather is launch #4 (profiled)
    k_gather<<<NCOL, 128>>>();
    k_rec1<<<(B * NHID) / 128, 128>>>();
    k_gemv2<<<700, 128>>>(W2);
    k_rec2<<<(B * NOUT + 127) / 128, 128>>>(out);
}